// round 2
// baseline (speedup 1.0000x reference)
#include <cuda_runtime.h>
#include <cstdint>

typedef unsigned long long u64;

#define T_STEPS 256
#define BATCH   8192

__device__ __forceinline__ void ffma2(u64& acc, u64 a, u64 b) {
    asm("fma.rn.f32x2 %0, %1, %2, %0;" : "+l"(acc) : "l"(a), "l"(b));
}
__device__ __forceinline__ u64 fadd2(u64 a, u64 b) {
    u64 d; asm("add.rn.f32x2 %0, %1, %2;" : "=l"(d) : "l"(a), "l"(b)); return d;
}
__device__ __forceinline__ u64 pack2(float lo, float hi) {
    u64 v; asm("mov.b64 %0, {%1, %2};" : "=l"(v) : "f"(lo), "f"(hi)); return v;
}
__device__ __forceinline__ float2 unpack2(u64 v) {
    float2 r; asm("mov.b64 {%0, %1}, %2;" : "=f"(r.x), "=f"(r.y) : "l"(v)); return r;
}

// One warp per batch element. 8 warps (8 batch elems) per 256-thread CTA.
__global__ __launch_bounds__(256, 2)
void snn_kernel(const float* __restrict__ x,
                const float* __restrict__ W1, const float* __restrict__ b1,
                const float* __restrict__ W2, const float* __restrict__ b2,
                const float* __restrict__ W3, const float* __restrict__ b3,
                float* __restrict__ out)
{
    __shared__ __align__(16) u64   xs[8][32];    // x[t,b] staged, 64 floats/warp
    __shared__ __align__(16) float s1s[8][32];   // layer-1 spikes (pad 28->32)
    __shared__ __align__(16) float s2s[8][16];   // layer-2 spikes (pad 14->16)
    __shared__ __align__(16) float w3s[16];      // W3 row (pad 14->16)

    const int lane = threadIdx.x & 31;
    const int w    = threadIdx.x >> 5;
    const int b    = blockIdx.x * 8 + w;

    // ---- preload weights (registers / shared) ----
    const int j1 = (lane < 28) ? lane : 27;        // lanes 28-31 duplicate row 27 (spike masked)
    const float b1j = b1[j1];
    u64 w1r[32];
    {
        const float4* wp = (const float4*)(W1 + j1 * 64);   // rows are 256B -> 16B aligned
        #pragma unroll
        for (int k = 0; k < 16; k++) {
            float4 v = wp[k];
            w1r[2*k]   = pack2(v.x, v.y);
            w1r[2*k+1] = pack2(v.z, v.w);
        }
    }
    const int j2 = lane % 14;
    const float b2j = b2[j2];
    u64 w2r[16];
    {
        const float4* wp = (const float4*)(W2 + j2 * 28);   // 28 floats = 112B, 16B aligned
        float tv[28];
        #pragma unroll
        for (int k = 0; k < 7; k++) {
            float4 v = wp[k];
            tv[4*k] = v.x; tv[4*k+1] = v.y; tv[4*k+2] = v.z; tv[4*k+3] = v.w;
        }
        #pragma unroll
        for (int m = 0; m < 14; m++) w2r[m] = pack2(tv[2*m], tv[2*m+1]);
        w2r[14] = 0ull; w2r[15] = 0ull;
    }
    if (threadIdx.x < 16)
        w3s[threadIdx.x] = (threadIdx.x < 14) ? W3[threadIdx.x] : 0.0f;
    const float b3v = b3[0];
    __syncthreads();

    // ---- time loop ----
    float mem1 = 0.0f, mem2 = 0.0f, mem3 = 0.0f;

    // x[t][b][d] @ (t*BATCH + b)*64 floats = (t*BATCH + b)*32 u64
    const u64* xp = (const u64*)x + (size_t)b * 32 + lane;
    const size_t tstride = (size_t)BATCH * 32;
    u64 xv = xp[0];                                 // prefetch t=0 (lane's 2 floats)

    #pragma unroll 1
    for (int t = 0; t < T_STEPS; t++) {
        xs[w][lane] = xv;                           // stage current x (coalesced STS.64)
        if (t + 1 < T_STEPS) xv = xp[(size_t)(t + 1) * tstride];   // prefetch next
        __syncwarp();

        // ---- layer 1: 28 neurons, one per lane ----
        const ulonglong2* xv2 = (const ulonglong2*)xs[w];
        u64 a0 = pack2(b1j, 0.0f), a1 = 0ull, a2 = 0ull, a3 = 0ull;
        #pragma unroll
        for (int k = 0; k < 8; k++) {
            ulonglong2 p = xv2[2*k];
            ulonglong2 q = xv2[2*k+1];
            ffma2(a0, p.x, w1r[4*k]);
            ffma2(a1, p.y, w1r[4*k+1]);
            ffma2(a2, q.x, w1r[4*k+2]);
            ffma2(a3, q.y, w1r[4*k+3]);
        }
        float2 c1 = unpack2(fadd2(fadd2(a0, a1), fadd2(a2, a3)));
        float cur1 = c1.x + c1.y;
        float reset1 = (mem1 > 1.0f) ? 1.0f : 0.0f;
        mem1 = fmaf(0.9f, mem1, cur1) - reset1;
        float s1 = (mem1 > 1.0f && lane < 28) ? 1.0f : 0.0f;

        s1s[w][lane] = s1;
        __syncwarp();

        // ---- layer 2: 14 neurons, lane j%14 (redundant on upper lanes) ----
        const ulonglong2* s1v = (const ulonglong2*)s1s[w];
        u64 g0 = pack2(b2j, 0.0f), g1 = 0ull;
        #pragma unroll
        for (int k = 0; k < 8; k++) {
            ulonglong2 p = s1v[k];
            ffma2(g0, p.x, w2r[2*k]);
            ffma2(g1, p.y, w2r[2*k+1]);
        }
        float2 c2 = unpack2(fadd2(g0, g1));
        float cur2 = c2.x + c2.y;
        float reset2 = (mem2 > 1.0f) ? 1.0f : 0.0f;
        mem2 = fmaf(0.9f, mem2, cur2) - reset2;
        float s2 = (mem2 > 1.0f) ? 1.0f : 0.0f;

        if (lane < 16) s2s[w][lane] = (lane < 14) ? s2 : 0.0f;
        __syncwarp();

        // ---- layer 3: 1 neuron (computed redundantly on all lanes) ----
        const ulonglong2* s2v = (const ulonglong2*)s2s[w];
        const ulonglong2* w3v = (const ulonglong2*)w3s;
        u64 h0 = 0ull, h1 = 0ull;
        #pragma unroll
        for (int k = 0; k < 4; k++) {
            ulonglong2 sv = s2v[k];
            ulonglong2 wv = w3v[k];
            ffma2(h0, sv.x, wv.x);
            ffma2(h1, sv.y, wv.y);
        }
        float2 c3 = unpack2(fadd2(h0, h1));
        float cur3 = c3.x + c3.y + b3v;
        float reset3 = (mem3 > 1.0f) ? 1.0f : 0.0f;
        mem3 = fmaf(0.9f, mem3, cur3) - reset3;

        if (lane == 0) out[t * BATCH + b] = mem3;
    }
}

extern "C" void kernel_launch(void* const* d_in, const int* in_sizes, int n_in,
                              void* d_out, int out_size) {
    const float* x  = (const float*)d_in[0];
    const float* W1 = (const float*)d_in[1];
    const float* b1 = (const float*)d_in[2];
    const float* W2 = (const float*)d_in[3];
    const float* b2 = (const float*)d_in[4];
    const float* W3 = (const float*)d_in[5];
    const float* b3 = (const float*)d_in[6];
    snn_kernel<<<BATCH / 8, 256>>>(x, W1, b1, W2, b2, W3, b3, (float*)d_out);
}

// round 3
// speedup vs baseline: 1.4228x; 1.4228x over previous
#include <cuda_runtime.h>
#include <cstdint>

typedef unsigned long long u64;

#define T_STEPS 256
#define BATCH   8192
#define NROWS   (T_STEPS * BATCH)      // 2,097,152

// scratch (device globals — no dynamic allocation)
__device__ float    g_cur1[(size_t)NROWS * 28];   // 235 MB
__device__ unsigned g_s1  [(size_t)NROWS];        // 8.4 MB
__device__ float    g_cur2[(size_t)NROWS * 14];   // 117 MB

__device__ __forceinline__ void ffma2(u64& acc, u64 a, u64 b) {
    asm("fma.rn.f32x2 %0, %1, %2, %0;" : "+l"(acc) : "l"(a), "l"(b));
}
__device__ __forceinline__ u64 fadd2(u64 a, u64 b) {
    u64 d; asm("add.rn.f32x2 %0, %1, %2;" : "=l"(d) : "l"(a), "l"(b)); return d;
}
__device__ __forceinline__ u64 pack2(float lo, float hi) {
    u64 v; asm("mov.b64 %0, {%1, %2};" : "=l"(v) : "f"(lo), "f"(hi)); return v;
}
__device__ __forceinline__ float2 unpack2(u64 v) {
    float2 r; asm("mov.b64 {%0, %1}, %2;" : "=f"(r.x), "=f"(r.y) : "l"(v)); return r;
}

// ---------------------------------------------------------------------------
// K1: cur1[r, j] = x[r, :] @ W1[j, :] + b1[j]   (r = t*BATCH + b, feed-forward)
// CTA = 256 thr (8 warps), tile = 64 rows staged in smem, 8 tiles/CTA.
// Lane j holds W1 row j in registers; x rows broadcast from smem.
// ---------------------------------------------------------------------------
#define K1_TILE 64
#define K1_TPC  8      // tiles per CTA
#define K1_CTAS (NROWS / (K1_TILE * K1_TPC))   // 4096

__global__ __launch_bounds__(256, 2)
void k1_gemm(const float* __restrict__ x, const float* __restrict__ W1,
             const float* __restrict__ b1)
{
    __shared__ __align__(16) u64 xs[2][K1_TILE][32];

    const int tid  = threadIdx.x;
    const int lane = tid & 31;
    const int w    = tid >> 5;
    const int j    = (lane < 28) ? lane : 27;

    u64 w1r[32];
    {
        const float4* wp = (const float4*)(W1 + j * 64);
        #pragma unroll
        for (int k = 0; k < 16; k++) {
            float4 v = wp[k];
            w1r[2*k]   = pack2(v.x, v.y);
            w1r[2*k+1] = pack2(v.z, v.w);
        }
    }
    const float bj = b1[j];

    const size_t row0 = (size_t)blockIdx.x * (K1_TILE * K1_TPC);

    // preload tile 0
    float4 pf[4];
    {
        const float4* xg = (const float4*)(x + row0 * 64);
        #pragma unroll
        for (int k = 0; k < 4; k++) pf[k] = xg[tid + k * 256];
        #pragma unroll
        for (int k = 0; k < 4; k++) ((float4*)xs[0])[tid + k * 256] = pf[k];
    }
    __syncthreads();

    for (int tile = 0; tile < K1_TPC; tile++) {
        const int buf = tile & 1;
        if (tile + 1 < K1_TPC) {
            const float4* xn = (const float4*)(x + (row0 + (size_t)(tile + 1) * K1_TILE) * 64);
            #pragma unroll
            for (int k = 0; k < 4; k++) pf[k] = xn[tid + k * 256];
        }
        #pragma unroll
        for (int r = 0; r < 8; r++) {
            const ulonglong2* xv = (const ulonglong2*)xs[buf][w * 8 + r];
            u64 a0 = pack2(bj, 0.0f), a1 = 0ull, a2 = 0ull, a3 = 0ull;
            #pragma unroll
            for (int k = 0; k < 8; k++) {
                ulonglong2 p = xv[2*k];
                ulonglong2 q = xv[2*k+1];
                ffma2(a0, p.x, w1r[4*k]);
                ffma2(a1, p.y, w1r[4*k+1]);
                ffma2(a2, q.x, w1r[4*k+2]);
                ffma2(a3, q.y, w1r[4*k+3]);
            }
            float2 c = unpack2(fadd2(fadd2(a0, a1), fadd2(a2, a3)));
            float cur = c.x + c.y;
            if (lane < 28)
                g_cur1[(row0 + tile * K1_TILE + w * 8 + r) * 28 + lane] = cur;
        }
        if (tile + 1 < K1_TPC) {
            #pragma unroll
            for (int k = 0; k < 4; k++) ((float4*)xs[buf ^ 1])[tid + k * 256] = pf[k];
        }
        __syncthreads();
    }
}

// ---------------------------------------------------------------------------
// K2: LIF1 scan. Warp per batch elem, lane = layer-1 neuron. Emits spike
// bitmask s1w[t*BATCH + b] (bits 0..27).
// ---------------------------------------------------------------------------
__global__ __launch_bounds__(256)
void k2_lif1()
{
    const int lane = threadIdx.x & 31;
    const int w    = threadIdx.x >> 5;
    const int b    = blockIdx.x * 8 + w;
    const int j    = (lane < 28) ? lane : 27;

    const float* p  = g_cur1 + (size_t)b * 28 + j;
    const size_t ts = (size_t)BATCH * 28;

    float mem = 0.0f;
    float cur = p[0];
    #pragma unroll 4
    for (int t = 0; t < T_STEPS; t++) {
        float nxt = p[(size_t)((t + 1 < T_STEPS) ? t + 1 : t) * ts];
        float reset = (mem > 1.0f) ? 1.0f : 0.0f;
        mem = fmaf(0.9f, mem, cur) - reset;
        unsigned m = __ballot_sync(0xffffffffu, mem > 1.0f) & 0x0FFFFFFFu;
        if (lane == 0) g_s1[(size_t)t * BATCH + b] = m;
        cur = nxt;
    }
}

// ---------------------------------------------------------------------------
// K3: cur2[e, j2] = b2[j2] + sum_{i: s1 bit set} W2[j2, i]. Thread per element,
// j2 vectorized in f32x2 pairs; W2^T pairs broadcast from smem.
// ---------------------------------------------------------------------------
__global__ __launch_bounds__(256)
void k3_cur2(const float* __restrict__ W2, const float* __restrict__ b2)
{
    __shared__ __align__(16) u64 w2t[28][8];   // [i][j-pair], pair p = (j=2p, 2p+1)
    __shared__ u64 b2p[7];

    const int tid = threadIdx.x;
    if (tid < 28) {
        #pragma unroll
        for (int p = 0; p < 8; p++) {
            u64 v = 0ull;
            if (p < 7) v = pack2(W2[(2*p) * 28 + tid], W2[(2*p + 1) * 28 + tid]);
            w2t[tid][p] = v;
        }
    }
    if (tid < 7) b2p[tid] = pack2(b2[2*tid], b2[2*tid + 1]);
    __syncthreads();

    const size_t e = (size_t)blockIdx.x * 256 + tid;
    const unsigned m = g_s1[e];

    u64 acc[7];
    #pragma unroll
    for (int p = 0; p < 7; p++) acc[p] = b2p[p];

    #pragma unroll
    for (int i = 0; i < 28; i++) {
        u64 sd = ((m >> i) & 1u) ? 0x3F8000003F800000ULL : 0ull;
        const ulonglong2* wr = (const ulonglong2*)w2t[i];
        ulonglong2 w01 = wr[0], w23 = wr[1], w45 = wr[2];
        u64 w6 = w2t[i][6];
        ffma2(acc[0], sd, w01.x); ffma2(acc[1], sd, w01.y);
        ffma2(acc[2], sd, w23.x); ffma2(acc[3], sd, w23.y);
        ffma2(acc[4], sd, w45.x); ffma2(acc[5], sd, w45.y);
        ffma2(acc[6], sd, w6);
    }

    u64* o = (u64*)(g_cur2 + e * 14);
    #pragma unroll
    for (int p = 0; p < 7; p++) o[p] = acc[p];
}

// ---------------------------------------------------------------------------
// K4: LIF2 scan + LIF3 + output. Warp = 2 batch elems (16-lane halves).
// Lane j<14 owns one layer-2 neuron; cur3 via 16-wide butterfly reduce.
// ---------------------------------------------------------------------------
__global__ __launch_bounds__(256)
void k4_lif23(const float* __restrict__ W3, const float* __restrict__ b3,
              float* __restrict__ out)
{
    const int lane = threadIdx.x & 31;
    const int w    = threadIdx.x >> 5;
    const int half = lane >> 4;
    const int j    = lane & 15;
    const int b    = (blockIdx.x * 8 + w) * 2 + half;
    const int jj   = (j < 14) ? j : 13;

    const float w3v = (j < 14) ? W3[j] : 0.0f;
    const float b3v = b3[0];

    const float* p  = g_cur2 + (size_t)b * 14 + jj;
    const size_t ts = (size_t)BATCH * 14;

    float mem2 = 0.0f, mem3 = 0.0f;
    float cur = p[0];
    #pragma unroll 2
    for (int t = 0; t < T_STEPS; t++) {
        float nxt = p[(size_t)((t + 1 < T_STEPS) ? t + 1 : t) * ts];
        float r2 = (mem2 > 1.0f) ? 1.0f : 0.0f;
        mem2 = fmaf(0.9f, mem2, cur) - r2;
        float v = (mem2 > 1.0f) ? w3v : 0.0f;
        v += __shfl_xor_sync(0xffffffffu, v, 1);
        v += __shfl_xor_sync(0xffffffffu, v, 2);
        v += __shfl_xor_sync(0xffffffffu, v, 4);
        v += __shfl_xor_sync(0xffffffffu, v, 8);
        float r3 = (mem3 > 1.0f) ? 1.0f : 0.0f;
        mem3 = fmaf(0.9f, mem3, v + b3v) - r3;
        if (j == 0) out[(size_t)t * BATCH + b] = mem3;
        cur = nxt;
    }
}

extern "C" void kernel_launch(void* const* d_in, const int* in_sizes, int n_in,
                              void* d_out, int out_size) {
    const float* x  = (const float*)d_in[0];
    const float* W1 = (const float*)d_in[1];
    const float* b1 = (const float*)d_in[2];
    const float* W2 = (const float*)d_in[3];
    const float* b2 = (const float*)d_in[4];
    const float* W3 = (const float*)d_in[5];
    const float* b3 = (const float*)d_in[6];
    float* out = (float*)d_out;

    k1_gemm <<<K1_CTAS, 256>>>(x, W1, b1);
    k2_lif1 <<<BATCH / 8, 256>>>();
    k3_cur2 <<<NROWS / 256, 256>>>(W2, b2);
    k4_lif23<<<BATCH / 16, 256>>>(W3, b3, out);
}

// round 4
// speedup vs baseline: 1.8079x; 1.2707x over previous
#include <cuda_runtime.h>
#include <cstdint>

typedef unsigned long long u64;

#define T_STEPS 256
#define BATCH   8192
#define NROWS   (T_STEPS * BATCH)      // 2,097,152

// scratch (device global — no dynamic allocation)
__device__ float g_cur1[(size_t)NROWS * 28];   // 235 MB

__device__ __forceinline__ void ffma2(u64& acc, u64 a, u64 b) {
    asm("fma.rn.f32x2 %0, %1, %2, %0;" : "+l"(acc) : "l"(a), "l"(b));
}
__device__ __forceinline__ u64 fadd2(u64 a, u64 b) {
    u64 d; asm("add.rn.f32x2 %0, %1, %2;" : "=l"(d) : "l"(a), "l"(b)); return d;
}
__device__ __forceinline__ u64 pack2(float lo, float hi) {
    u64 v; asm("mov.b64 %0, {%1, %2};" : "=l"(v) : "f"(lo), "f"(hi)); return v;
}
__device__ __forceinline__ float2 unpack2(u64 v) {
    float2 r; asm("mov.b64 {%0, %1}, %2;" : "=f"(r.x), "=f"(r.y) : "l"(v)); return r;
}

// ---------------------------------------------------------------------------
// K1: cur1[r, j] = x[r, :] @ W1[j, :] + b1[j]   (r = t*BATCH + b, feed-forward)
// ---------------------------------------------------------------------------
#define K1_TILE 64
#define K1_TPC  8
#define K1_CTAS (NROWS / (K1_TILE * K1_TPC))   // 4096

__global__ __launch_bounds__(256, 2)
void k1_gemm(const float* __restrict__ x, const float* __restrict__ W1,
             const float* __restrict__ b1)
{
    __shared__ __align__(16) u64 xs[2][K1_TILE][32];

    const int tid  = threadIdx.x;
    const int lane = tid & 31;
    const int w    = tid >> 5;
    const int j    = (lane < 28) ? lane : 27;

    u64 w1r[32];
    {
        const float4* wp = (const float4*)(W1 + j * 64);
        #pragma unroll
        for (int k = 0; k < 16; k++) {
            float4 v = wp[k];
            w1r[2*k]   = pack2(v.x, v.y);
            w1r[2*k+1] = pack2(v.z, v.w);
        }
    }
    const float bj = b1[j];

    const size_t row0 = (size_t)blockIdx.x * (K1_TILE * K1_TPC);

    float4 pf[4];
    {
        const float4* xg = (const float4*)(x + row0 * 64);
        #pragma unroll
        for (int k = 0; k < 4; k++) pf[k] = xg[tid + k * 256];
        #pragma unroll
        for (int k = 0; k < 4; k++) ((float4*)xs[0])[tid + k * 256] = pf[k];
    }
    __syncthreads();

    for (int tile = 0; tile < K1_TPC; tile++) {
        const int buf = tile & 1;
        if (tile + 1 < K1_TPC) {
            const float4* xn = (const float4*)(x + (row0 + (size_t)(tile + 1) * K1_TILE) * 64);
            #pragma unroll
            for (int k = 0; k < 4; k++) pf[k] = xn[tid + k * 256];
        }
        #pragma unroll
        for (int r = 0; r < 8; r++) {
            const ulonglong2* xv = (const ulonglong2*)xs[buf][w * 8 + r];
            u64 a0 = pack2(bj, 0.0f), a1 = 0ull, a2 = 0ull, a3 = 0ull;
            #pragma unroll
            for (int k = 0; k < 8; k++) {
                ulonglong2 p = xv[2*k];
                ulonglong2 q = xv[2*k+1];
                ffma2(a0, p.x, w1r[4*k]);
                ffma2(a1, p.y, w1r[4*k+1]);
                ffma2(a2, q.x, w1r[4*k+2]);
                ffma2(a3, q.y, w1r[4*k+3]);
            }
            float2 c = unpack2(fadd2(fadd2(a0, a1), fadd2(a2, a3)));
            float cur = c.x + c.y;
            if (lane < 28)
                g_cur1[(row0 + tile * K1_TILE + w * 8 + r) * 28 + lane] = cur;
        }
        if (tile + 1 < K1_TPC) {
            #pragma unroll
            for (int k = 0; k < 4; k++) ((float4*)xs[buf ^ 1])[tid + k * 256] = pf[k];
        }
        __syncthreads();
    }
}

// ---------------------------------------------------------------------------
// K234: fused LIF1 scan + layer2 (LUT) + layer3 (LUT) + output.
// Warp = 2 batch elems (16-lane halves). Lane j (=lane&15, j<14 active):
//   - owns layer-1 neurons (2j, 2j+1) of its half's batch elem (f32x2 pair)
//   - owns layer-2 neuron j of its half's batch elem
// Spike masks via ballot; W2/W3 contributions via smem LUTs (7-bit groups).
// ---------------------------------------------------------------------------
__global__ __launch_bounds__(256)
void k234_scan(const float* __restrict__ W2, const float* __restrict__ b2,
               const float* __restrict__ W3, const float* __restrict__ b3,
               float* __restrict__ out)
{
    // LUT2[g][m][j2]: g0 = even neurons 2k (k=0..6), g1 = even 2k+14,
    //                 g2 = odd 2k+1,               g3 = odd 2k+15
    __shared__ __align__(16) float LUT2[4][128][16];
    __shared__ float L3s[2][128];

    const int tid = threadIdx.x;

    for (int e = tid; e < 512; e += 256) {
        const int g = e >> 7, m = e & 127;
        const int odd  = (g >= 2) ? 1 : 0;
        const int base = (g & 1) ? 14 : 0;
        #pragma unroll
        for (int j2 = 0; j2 < 14; j2++) {
            float s = 0.0f;
            #pragma unroll
            for (int k = 0; k < 7; k++)
                if (m & (1 << k)) s += W2[j2 * 28 + (2 * k + odd + base)];
            LUT2[g][m][j2] = s;
        }
        if (tid + 256 >= 512 || e >= 256) {} // no-op
    }
    for (int e = tid; e < 256; e += 256) {
        const int g = e >> 7, m = e & 127;
        float s = 0.0f;
        #pragma unroll
        for (int k = 0; k < 7; k++)
            if (m & (1 << k)) s += W3[g * 7 + k];
        L3s[g][m] = s;
    }
    __syncthreads();

    const int lane = tid & 31;
    const int half = lane >> 4;
    const int j    = lane & 15;
    const int jj   = (j < 14) ? j : 13;
    const bool act = (j < 14);
    const unsigned sh = half << 4;

    const int gw = blockIdx.x * 8 + (tid >> 5);
    const int bb = gw * 2 + half;

    const float b2j = b2[jj];
    const float b3v = b3[0];

    const float* basep = g_cur1 + ((size_t)bb * 28 + (size_t)jj * 2);
    const size_t ts = (size_t)BATCH * 28;

    float m1a = 0.0f, m1b = 0.0f, m2 = 0.0f, m3 = 0.0f;

    #define LD_T(tt) (*(const u64*)(basep + (size_t)(tt) * ts))
    u64 pf0 = LD_T(0), pf1 = LD_T(1), pf2 = LD_T(2), pf3 = LD_T(3);

    #define STEP(t, cur) do {                                                   \
        float2 c = unpack2(cur);                                                \
        float r1a = (m1a > 1.0f) ? 1.0f : 0.0f;                                 \
        m1a = fmaf(0.9f, m1a, c.x) - r1a;                                       \
        float r1b = (m1b > 1.0f) ? 1.0f : 0.0f;                                 \
        m1b = fmaf(0.9f, m1b, c.y) - r1b;                                       \
        unsigned balA = __ballot_sync(0xffffffffu, (m1a > 1.0f) & act);         \
        unsigned balB = __ballot_sync(0xffffffffu, (m1b > 1.0f) & act);         \
        unsigned ma = (balA >> sh) & 0x3FFFu;                                   \
        unsigned mb = (balB >> sh) & 0x3FFFu;                                   \
        float cur2 = b2j + LUT2[0][ma & 127u][jj] + LUT2[1][ma >> 7][jj]        \
                         + LUT2[2][mb & 127u][jj] + LUT2[3][mb >> 7][jj];       \
        float r2 = (m2 > 1.0f) ? 1.0f : 0.0f;                                   \
        m2 = fmaf(0.9f, m2, cur2) - r2;                                         \
        unsigned bal2 = __ballot_sync(0xffffffffu, (m2 > 1.0f) & act);          \
        unsigned mm = (bal2 >> sh) & 0x3FFFu;                                   \
        float cur3 = b3v + L3s[0][mm & 127u] + L3s[1][mm >> 7];                 \
        float r3 = (m3 > 1.0f) ? 1.0f : 0.0f;                                   \
        m3 = fmaf(0.9f, m3, cur3) - r3;                                         \
        if (j == 0) out[(size_t)(t) * BATCH + bb] = m3;                         \
    } while (0)

    #pragma unroll 1
    for (int t = 0; t < T_STEPS; t += 4) {
        int t4 = (t + 4 < T_STEPS) ? t + 4 : T_STEPS - 1;
        int t5 = (t + 5 < T_STEPS) ? t + 5 : T_STEPS - 1;
        int t6 = (t + 6 < T_STEPS) ? t + 6 : T_STEPS - 1;
        int t7 = (t + 7 < T_STEPS) ? t + 7 : T_STEPS - 1;
        STEP(t,     pf0); pf0 = LD_T(t4);
        STEP(t + 1, pf1); pf1 = LD_T(t5);
        STEP(t + 2, pf2); pf2 = LD_T(t6);
        STEP(t + 3, pf3); pf3 = LD_T(t7);
    }
    #undef STEP
    #undef LD_T
}

extern "C" void kernel_launch(void* const* d_in, const int* in_sizes, int n_in,
                              void* d_out, int out_size) {
    const float* x  = (const float*)d_in[0];
    const float* W1 = (const float*)d_in[1];
    const float* b1 = (const float*)d_in[2];
    const float* W2 = (const float*)d_in[3];
    const float* b2 = (const float*)d_in[4];
    const float* W3 = (const float*)d_in[5];
    const float* b3 = (const float*)d_in[6];
    float* out = (float*)d_out;

    k1_gemm  <<<K1_CTAS, 256>>>(x, W1, b1);
    k234_scan<<<BATCH / 16, 256>>>(W2, b2, W3, b3, out);
}

// round 5
// speedup vs baseline: 2.1165x; 1.1707x over previous
#include <cuda_runtime.h>
#include <cstdint>

typedef unsigned long long u64;

#define T_STEPS 256
#define BATCH   8192
#define DEPTH   8            // cp.async ring slots (effective lead = 7 steps)

__device__ __forceinline__ void ffma2(u64& acc, u64 a, u64 b) {
    asm("fma.rn.f32x2 %0, %1, %2, %0;" : "+l"(acc) : "l"(a), "l"(b));
}
__device__ __forceinline__ u64 fadd2(u64 a, u64 b) {
    u64 d; asm("add.rn.f32x2 %0, %1, %2;" : "=l"(d) : "l"(a), "l"(b)); return d;
}
__device__ __forceinline__ u64 pack2(float lo, float hi) {
    u64 v; asm("mov.b64 %0, {%1, %2};" : "=l"(v) : "f"(lo), "f"(hi)); return v;
}
__device__ __forceinline__ float2 unpack2(u64 v) {
    float2 r; asm("mov.b64 {%0, %1}, %2;" : "=f"(r.x), "=f"(r.y) : "l"(v)); return r;
}
__device__ __forceinline__ unsigned smem_u32(const void* p) {
    unsigned a;
    asm("{ .reg .u64 t; cvta.to.shared.u64 t, %1; cvt.u32.u64 %0, t; }" : "=r"(a) : "l"(p));
    return a;
}
__device__ __forceinline__ void cp_async8(unsigned dst, const void* src) {
    asm volatile("cp.async.ca.shared.global [%0], [%1], 8;" :: "r"(dst), "l"(src));
}
__device__ __forceinline__ void cp_commit() {
    asm volatile("cp.async.commit_group;" ::: "memory");
}
__device__ __forceinline__ void cp_wait7() {
    asm volatile("cp.async.wait_group 7;" ::: "memory");
}

// One warp = one batch element. Lane j<28 owns L1 neuron j; lane j<14 owns L2
// neuron j. Spikes exchanged via ballot; W2/W3 sums via smem LUTs over 7-bit
// spike-mask groups. x streamed through a per-warp cp.async ring (no barriers).
__global__ __launch_bounds__(256, 2)
void snn_all(const float* __restrict__ x,
             const float* __restrict__ W1, const float* __restrict__ b1,
             const float* __restrict__ W2, const float* __restrict__ b2,
             const float* __restrict__ W3, const float* __restrict__ b3,
             float* __restrict__ out)
{
    __shared__ __align__(16) u64 xring[8][DEPTH][32];   // 16 KB
    __shared__ float LUT2[4][128][14];                  // 28 KB
    __shared__ float L3s[2][128];                       // 1 KB

    const int tid = threadIdx.x;

    // ---- build LUTs: LUT2[g][m][j] = sum_{k: m bit k} W2[j, 7g+k] ----
    for (int e = tid; e < 512; e += 256) {
        const int g = e >> 7, m = e & 127;
        #pragma unroll
        for (int j = 0; j < 14; j++) {
            float s = 0.0f;
            #pragma unroll
            for (int k = 0; k < 7; k++)
                if (m & (1 << k)) s += W2[j * 28 + 7 * g + k];
            LUT2[g][m][j] = s;
        }
    }
    {
        const int g = tid >> 7, m = tid & 127;
        float s = 0.0f;
        #pragma unroll
        for (int k = 0; k < 7; k++)
            if (m & (1 << k)) s += W3[7 * g + k];
        L3s[g][m] = s;
    }

    const int lane = tid & 31;
    const int w    = tid >> 5;
    const int b    = blockIdx.x * 8 + w;
    const int j1   = (lane < 28) ? lane : 27;
    const int j2   = (lane < 14) ? lane : 13;

    // ---- W1 row in registers (packed f32x2) ----
    u64 w1r[32];
    {
        const float4* wp = (const float4*)(W1 + j1 * 64);
        #pragma unroll
        for (int k = 0; k < 16; k++) {
            float4 v = wp[k];
            w1r[2*k]   = pack2(v.x, v.y);
            w1r[2*k+1] = pack2(v.z, v.w);
        }
    }
    const float b1j = b1[j1];
    const float b2j = b2[j2];
    const float b3v = b3[0];

    __syncthreads();   // LUTs ready

    // ---- cp.async ring: lane copies its 8B chunk of x[t, b, :] ----
    const float* xg = x + (size_t)b * 64 + lane * 2;
    const size_t tstride = (size_t)BATCH * 64;
    const unsigned ring0 = smem_u32(&xring[w][0][0]) + lane * 8;

    #pragma unroll
    for (int d = 0; d < DEPTH - 1; d++) {      // prefill 7 groups
        cp_async8(ring0 + d * 256, xg + (size_t)d * tstride);
        cp_commit();
    }

    float m1 = 0.0f, m2 = 0.0f, m3 = 0.0f;

    #pragma unroll 2
    for (int t = 0; t < T_STEPS; t++) {
        // issue copy for t+7 (slot != slot being consumed this iter)
        const int tn = t + DEPTH - 1;
        if (tn < T_STEPS)
            cp_async8(ring0 + (tn & (DEPTH - 1)) * 256, xg + (size_t)tn * tstride);
        cp_commit();
        cp_wait7();            // oldest group (this t) complete
        __syncwarp();

        // ---- layer 1 dot product (broadcast LDS.128 + FFMA2) ----
        const ulonglong2* xv = (const ulonglong2*)&xring[w][t & (DEPTH - 1)][0];
        u64 a0 = pack2(b1j, 0.0f), a1 = 0ull, a2 = 0ull, a3 = 0ull;
        #pragma unroll
        for (int k = 0; k < 8; k++) {
            ulonglong2 p = xv[2*k];
            ulonglong2 q = xv[2*k+1];
            ffma2(a0, p.x, w1r[4*k]);
            ffma2(a1, p.y, w1r[4*k+1]);
            ffma2(a2, q.x, w1r[4*k+2]);
            ffma2(a3, q.y, w1r[4*k+3]);
        }
        float2 c = unpack2(fadd2(fadd2(a0, a1), fadd2(a2, a3)));
        float cur1 = c.x + c.y;

        // ---- LIF1 + spike ballot ----
        float r1 = (m1 > 1.0f) ? 1.0f : 0.0f;
        m1 = fmaf(0.9f, m1, cur1) - r1;
        unsigned s1 = __ballot_sync(0xffffffffu, m1 > 1.0f) & 0x0FFFFFFFu;

        // ---- layer 2 via LUT ----
        float cur2 = b2j + LUT2[0][s1 & 127u][j2]
                         + LUT2[1][(s1 >> 7) & 127u][j2]
                         + LUT2[2][(s1 >> 14) & 127u][j2]
                         + LUT2[3][s1 >> 21][j2];
        float r2 = (m2 > 1.0f) ? 1.0f : 0.0f;
        m2 = fmaf(0.9f, m2, cur2) - r2;
        unsigned s2 = __ballot_sync(0xffffffffu, m2 > 1.0f) & 0x3FFFu;

        // ---- layer 3 via LUT ----
        float cur3 = b3v + L3s[0][s2 & 127u] + L3s[1][s2 >> 7];
        float r3 = (m3 > 1.0f) ? 1.0f : 0.0f;
        m3 = fmaf(0.9f, m3, cur3) - r3;

        if (lane == 0) out[(size_t)t * BATCH + b] = m3;
    }
}

extern "C" void kernel_launch(void* const* d_in, const int* in_sizes, int n_in,
                              void* d_out, int out_size) {
    const float* x  = (const float*)d_in[0];
    const float* W1 = (const float*)d_in[1];
    const float* b1 = (const float*)d_in[2];
    const float* W2 = (const float*)d_in[3];
    const float* b2 = (const float*)d_in[4];
    const float* W3 = (const float*)d_in[5];
    const float* b3 = (const float*)d_in[6];
    snn_all<<<BATCH / 8, 256>>>(x, W1, b1, W2, b2, W3, b3, (float*)d_out);
}

// round 6
// speedup vs baseline: 2.3042x; 1.0887x over previous
#include <cuda_runtime.h>
#include <cstdint>

typedef unsigned long long u64;

#define T_STEPS 256
#define BATCH   8192
#define DEPTH   8            // ring slots (steps); commit granularity = 2 steps

__device__ __forceinline__ void ffma2(u64& acc, u64 a, u64 b) {
    asm("fma.rn.f32x2 %0, %1, %2, %0;" : "+l"(acc) : "l"(a), "l"(b));
}
__device__ __forceinline__ u64 fadd2(u64 a, u64 b) {
    u64 d; asm("add.rn.f32x2 %0, %1, %2;" : "=l"(d) : "l"(a), "l"(b)); return d;
}
__device__ __forceinline__ u64 pack2(float lo, float hi) {
    u64 v; asm("mov.b64 %0, {%1, %2};" : "=l"(v) : "f"(lo), "f"(hi)); return v;
}
__device__ __forceinline__ float2 unpack2(u64 v) {
    float2 r; asm("mov.b64 {%0, %1}, %2;" : "=f"(r.x), "=f"(r.y) : "l"(v)); return r;
}
__device__ __forceinline__ unsigned smem_u32(const void* p) {
    unsigned a;
    asm("{ .reg .u64 t; cvta.to.shared.u64 t, %1; cvt.u32.u64 %0, t; }" : "=r"(a) : "l"(p));
    return a;
}
__device__ __forceinline__ void cp_async8(unsigned dst, const void* src) {
    asm volatile("cp.async.ca.shared.global [%0], [%1], 8;" :: "r"(dst), "l"(src));
}
__device__ __forceinline__ void cp_commit() {
    asm volatile("cp.async.commit_group;" ::: "memory");
}
__device__ __forceinline__ void cp_wait3() {
    asm volatile("cp.async.wait_group 3;" ::: "memory");
}

// One warp = one batch element. Lane j<28 owns L1 neuron j; lane j<14 owns L2
// neuron j. Spikes via ballot; W2/W3 sums via smem LUTs (7-bit mask groups).
// x streamed through a per-warp cp.async ring; steps processed in PAIRS with
// one wait/sync per pair so the t+1 GEMM overlaps the t LIF/LUT latency chain.
__global__ __launch_bounds__(256, 2)
void snn_all(const float* __restrict__ x,
             const float* __restrict__ W1, const float* __restrict__ b1,
             const float* __restrict__ W2, const float* __restrict__ b2,
             const float* __restrict__ W3, const float* __restrict__ b3,
             float* __restrict__ out)
{
    __shared__ __align__(16) u64 xring[8][DEPTH][32];   // 16 KB
    __shared__ float LUT2[4][128][14];                  // 28 KB
    __shared__ float L3s[2][128];                       // 1 KB

    const int tid = threadIdx.x;

    // ---- build LUTs: LUT2[g][m][j] = sum_{k: m bit k} W2[j, 7g+k] ----
    for (int e = tid; e < 512; e += 256) {
        const int g = e >> 7, m = e & 127;
        #pragma unroll
        for (int j = 0; j < 14; j++) {
            float s = 0.0f;
            #pragma unroll
            for (int k = 0; k < 7; k++)
                if (m & (1 << k)) s += W2[j * 28 + 7 * g + k];
            LUT2[g][m][j] = s;
        }
    }
    {
        const int g = tid >> 7, m = tid & 127;
        float s = 0.0f;
        #pragma unroll
        for (int k = 0; k < 7; k++)
            if (m & (1 << k)) s += W3[7 * g + k];
        L3s[g][m] = s;
    }

    const int lane = tid & 31;
    const int w    = tid >> 5;
    const int b    = blockIdx.x * 8 + w;
    const int j1   = (lane < 28) ? lane : 27;
    const int j2   = (lane < 14) ? lane : 13;

    // ---- W1 row in registers (packed f32x2) ----
    u64 w1r[32];
    {
        const float4* wp = (const float4*)(W1 + j1 * 64);
        #pragma unroll
        for (int k = 0; k < 16; k++) {
            float4 v = wp[k];
            w1r[2*k]   = pack2(v.x, v.y);
            w1r[2*k+1] = pack2(v.z, v.w);
        }
    }
    const float b1j = b1[j1];
    const float b2j = b2[j2];
    const float b3v = b3[0];

    __syncthreads();   // LUTs ready

    // ---- cp.async ring: lane copies its 8B chunk of x[t, b, :] ----
    const float* xg = x + (size_t)b * 64 + lane * 2;
    const size_t tstride = (size_t)BATCH * 64;
    const unsigned ring0 = smem_u32(&xring[w][0][0]) + lane * 8;

    // prefill 3 pairs (steps 0..5), one commit group per pair
    #pragma unroll
    for (int d = 0; d < 3; d++) {
        cp_async8(ring0 + (2*d)     * 256, xg + (size_t)(2*d)     * tstride);
        cp_async8(ring0 + (2*d + 1) * 256, xg + (size_t)(2*d + 1) * tstride);
        cp_commit();
    }

    float m1 = 0.0f, m2 = 0.0f, m3 = 0.0f;

    // one full LIF step given cur1 (current into layer 1 for this lane)
    #define LIF_STEP(t, cur1) do {                                              \
        float r1 = (m1 > 1.0f) ? 1.0f : 0.0f;                                   \
        m1 = fmaf(0.9f, m1, (cur1)) - r1;                                       \
        unsigned s1 = __ballot_sync(0xffffffffu, m1 > 1.0f) & 0x0FFFFFFFu;      \
        float cur2 = b2j + (LUT2[0][s1 & 127u][j2]                              \
                          + LUT2[1][(s1 >> 7) & 127u][j2])                      \
                         + (LUT2[2][(s1 >> 14) & 127u][j2]                      \
                          + LUT2[3][s1 >> 21][j2]);                             \
        float r2 = (m2 > 1.0f) ? 1.0f : 0.0f;                                   \
        m2 = fmaf(0.9f, m2, cur2) - r2;                                         \
        unsigned s2 = __ballot_sync(0xffffffffu, m2 > 1.0f) & 0x3FFFu;          \
        float cur3 = b3v + (L3s[0][s2 & 127u] + L3s[1][s2 >> 7]);               \
        float r3 = (m3 > 1.0f) ? 1.0f : 0.0f;                                   \
        m3 = fmaf(0.9f, m3, cur3) - r3;                                         \
        if (lane == 0) out[(size_t)(t) * BATCH + b] = m3;                       \
    } while (0)

    // layer-1 dot product from ring slot s into cur1
    #define GEMM(s, cur1) do {                                                  \
        const ulonglong2* xv = (const ulonglong2*)&xring[w][(s)][0];            \
        u64 a0 = pack2(b1j, 0.0f), a1 = 0ull, a2 = 0ull, a3 = 0ull;             \
        _Pragma("unroll")                                                       \
        for (int k = 0; k < 8; k++) {                                           \
            ulonglong2 p = xv[2*k];                                             \
            ulonglong2 q = xv[2*k+1];                                           \
            ffma2(a0, p.x, w1r[4*k]);                                           \
            ffma2(a1, p.y, w1r[4*k+1]);                                         \
            ffma2(a2, q.x, w1r[4*k+2]);                                         \
            ffma2(a3, q.y, w1r[4*k+3]);                                         \
        }                                                                       \
        float2 c = unpack2(fadd2(fadd2(a0, a1), fadd2(a2, a3)));                \
        (cur1) = c.x + c.y;                                                     \
    } while (0)

    #pragma unroll 1
    for (int t = 0; t < T_STEPS; t += 2) {
        // issue pair t+6, t+7 (slots disjoint from the pair being consumed)
        const int tn = t + 6;
        if (tn < T_STEPS) {
            cp_async8(ring0 + (tn & (DEPTH - 1)) * 256,       xg + (size_t)tn * tstride);
            cp_async8(ring0 + ((tn + 1) & (DEPTH - 1)) * 256, xg + (size_t)(tn + 1) * tstride);
        }
        cp_commit();
        cp_wait3();            // pair t complete
        __syncwarp();

        // both GEMMs first (independent of the recurrent chain) — ptxas can
        // schedule step-(t+1) loads/FFMAs under step-t's LIF/LUT latency.
        float cur1a, cur1b;
        GEMM(t & (DEPTH - 1), cur1a);
        GEMM((t + 1) & (DEPTH - 1), cur1b);

        LIF_STEP(t,     cur1a);
        LIF_STEP(t + 1, cur1b);
    }
    #undef GEMM
    #undef LIF_STEP
}

extern "C" void kernel_launch(void* const* d_in, const int* in_sizes, int n_in,
                              void* d_out, int out_size) {
    const float* x  = (const float*)d_in[0];
    const float* W1 = (const float*)d_in[1];
    const float* b1 = (const float*)d_in[2];
    const float* W2 = (const float*)d_in[3];
    const float* b2 = (const float*)d_in[4];
    const float* W3 = (const float*)d_in[5];
    const float* b3 = (const float*)d_in[6];
    snn_all<<<BATCH / 8, 256>>>(x, W1, b1, W2, b2, W3, b3, (float*)d_out);
}

// round 11
// speedup vs baseline: 2.3412x; 1.0161x over previous
#include <cuda_runtime.h>
#include <cstdint>

typedef unsigned long long u64;

#define T_STEPS 256
#define BATCH   8192
#define DEPTH   16           // ring slots (steps); commit granularity = 4 steps

__device__ __forceinline__ void ffma2(u64& acc, u64 a, u64 b) {
    asm("fma.rn.f32x2 %0, %1, %2, %0;" : "+l"(acc) : "l"(a), "l"(b));
}
__device__ __forceinline__ u64 fadd2(u64 a, u64 b) {
    u64 d; asm("add.rn.f32x2 %0, %1, %2;" : "=l"(d) : "l"(a), "l"(b)); return d;
}
__device__ __forceinline__ u64 pack2(float lo, float hi) {
    u64 v; asm("mov.b64 %0, {%1, %2};" : "=l"(v) : "f"(lo), "f"(hi)); return v;
}
__device__ __forceinline__ float2 unpack2(u64 v) {
    float2 r; asm("mov.b64 {%0, %1}, %2;" : "=f"(r.x), "=f"(r.y) : "l"(v)); return r;
}
__device__ __forceinline__ unsigned smem_u32(const void* p) {
    unsigned a;
    asm("{ .reg .u64 t; cvta.to.shared.u64 t, %1; cvt.u32.u64 %0, t; }" : "=r"(a) : "l"(p));
    return a;
}
__device__ __forceinline__ void cp_async8(unsigned dst, const void* src) {
    asm volatile("cp.async.ca.shared.global [%0], [%1], 8;" :: "r"(dst), "l"(src));
}
__device__ __forceinline__ void cp_commit() {
    asm volatile("cp.async.commit_group;" ::: "memory");
}
__device__ __forceinline__ void cp_wait3() {
    asm volatile("cp.async.wait_group 3;" ::: "memory");
}

// One warp = one batch element. Lane j<28 owns L1 neuron j; lane j<14 owns L2
// neuron j. Spikes via ballot; W2/W3 sums via smem LUTs (7-bit mask groups).
// x streamed via per-warp cp.async ring; 4 steps per commit/wait/sync block,
// all 4 GEMMs hoisted ahead of the 4 serial LIF chains.
// NOTE: GEMM accumulation order is part of the correctness contract (spike
// decisions flip under reassociation) — keep the 4-chain order from R6 exactly.
__global__ __launch_bounds__(256, 2)
void snn_all(const float* __restrict__ x,
             const float* __restrict__ W1, const float* __restrict__ b1,
             const float* __restrict__ W2, const float* __restrict__ b2,
             const float* __restrict__ W3, const float* __restrict__ b3,
             float* __restrict__ out)
{
    __shared__ __align__(16) u64 xring[8][DEPTH][32];   // 32 KB
    __shared__ float LUT2[4][128][16];                  // 32 KB (j padded 14->16)
    __shared__ float L3s[2][128];                       // 1 KB

    const int tid = threadIdx.x;

    // ---- build LUTs: LUT2[g][m][j] = sum_{k: m bit k} W2[j, 7g+k] ----
    for (int e = tid; e < 512; e += 256) {
        const int g = e >> 7, m = e & 127;
        #pragma unroll
        for (int j = 0; j < 16; j++) {
            float s = 0.0f;
            if (j < 14) {
                #pragma unroll
                for (int k = 0; k < 7; k++)
                    if (m & (1 << k)) s += W2[j * 28 + 7 * g + k];
            }
            LUT2[g][m][j] = s;
        }
    }
    {
        const int g = tid >> 7, m = tid & 127;
        float s = 0.0f;
        #pragma unroll
        for (int k = 0; k < 7; k++)
            if (m & (1 << k)) s += W3[7 * g + k];
        L3s[g][m] = s;
    }

    const int lane = tid & 31;
    const int w    = tid >> 5;
    const int b    = blockIdx.x * 8 + w;
    const int j1   = (lane < 28) ? lane : 27;
    const int j2   = (lane < 14) ? lane : 13;

    // ---- W1 row in registers (packed f32x2) ----
    u64 w1r[32];
    {
        const float4* wp = (const float4*)(W1 + j1 * 64);
        #pragma unroll
        for (int k = 0; k < 16; k++) {
            float4 v = wp[k];
            w1r[2*k]   = pack2(v.x, v.y);
            w1r[2*k+1] = pack2(v.z, v.w);
        }
    }
    const float b1j = b1[j1];
    const float b2j = b2[j2];
    const float b3v = b3[0];

    __syncthreads();   // LUTs ready

    // ---- cp.async ring: lane copies its 8B chunk of x[t, b, :] ----
    const float* xg = x + (size_t)b * 64 + lane * 2;
    const size_t tstride = (size_t)BATCH * 64;
    const unsigned ring0 = smem_u32(&xring[w][0][0]) + lane * 8;

    // prefill groups for steps 0..11, one commit group per 4 steps
    #pragma unroll
    for (int gidx = 0; gidx < 3; gidx++) {
        #pragma unroll
        for (int s = 0; s < 4; s++) {
            const int tt = gidx * 4 + s;
            cp_async8(ring0 + tt * 256, xg + (size_t)tt * tstride);
        }
        cp_commit();
    }

    float m1 = 0.0f, m2 = 0.0f, m3 = 0.0f;

    #define LIF_STEP(t, cur1) do {                                              \
        float r1 = (m1 > 1.0f) ? 1.0f : 0.0f;                                   \
        m1 = fmaf(0.9f, m1, (cur1)) - r1;                                       \
        unsigned s1 = __ballot_sync(0xffffffffu, m1 > 1.0f) & 0x0FFFFFFFu;      \
        float cur2 = b2j + (LUT2[0][s1 & 127u][j2]                              \
                          + LUT2[1][(s1 >> 7) & 127u][j2])                      \
                         + (LUT2[2][(s1 >> 14) & 127u][j2]                      \
                          + LUT2[3][s1 >> 21][j2]);                             \
        float r2 = (m2 > 1.0f) ? 1.0f : 0.0f;                                   \
        m2 = fmaf(0.9f, m2, cur2) - r2;                                         \
        unsigned s2 = __ballot_sync(0xffffffffu, m2 > 1.0f) & 0x3FFFu;          \
        float cur3 = b3v + (L3s[0][s2 & 127u] + L3s[1][s2 >> 7]);               \
        float r3 = (m3 > 1.0f) ? 1.0f : 0.0f;                                   \
        m3 = fmaf(0.9f, m3, cur3) - r3;                                         \
        if (lane == 0) out[(size_t)(t) * BATCH + b] = m3;                       \
    } while (0)

    // layer-1 dot product from ring slot s — EXACT 4-accumulator order of R6
    #define GEMM(s, cur1) do {                                                  \
        const ulonglong2* xv = (const ulonglong2*)&xring[w][(s)][0];            \
        u64 a0 = pack2(b1j, 0.0f), a1 = 0ull, a2 = 0ull, a3 = 0ull;             \
        _Pragma("unroll")                                                       \
        for (int k = 0; k < 8; k++) {                                           \
            ulonglong2 p = xv[2*k];                                             \
            ulonglong2 q = xv[2*k+1];                                           \
            ffma2(a0, p.x, w1r[4*k]);                                           \
            ffma2(a1, p.y, w1r[4*k+1]);                                         \
            ffma2(a2, q.x, w1r[4*k+2]);                                         \
            ffma2(a3, q.y, w1r[4*k+3]);                                         \
        }                                                                       \
        float2 c = unpack2(fadd2(fadd2(a0, a1), fadd2(a2, a3)));                \
        (cur1) = c.x + c.y;                                                     \
    } while (0)

    #pragma unroll 1
    for (int t = 0; t < T_STEPS; t += 4) {
        // issue group for steps t+12..t+15 (slots disjoint from t..t+3)
        const int tn = t + 12;
        if (tn < T_STEPS) {
            #pragma unroll
            for (int s = 0; s < 4; s++)
                cp_async8(ring0 + ((tn + s) & (DEPTH - 1)) * 256,
                          xg + (size_t)(tn + s) * tstride);
        }
        cp_commit();
        cp_wait3();            // group for steps t..t+3 complete
        __syncwarp();

        // all four GEMMs first — independent of the recurrent chain
        float c0, c1, c2, c3;
        GEMM((t)     & (DEPTH - 1), c0);
        GEMM((t + 1) & (DEPTH - 1), c1);
        GEMM((t + 2) & (DEPTH - 1), c2);
        GEMM((t + 3) & (DEPTH - 1), c3);

        LIF_STEP(t,     c0);
        LIF_STEP(t + 1, c1);
        LIF_STEP(t + 2, c2);
        LIF_STEP(t + 3, c3);
    }
    #undef GEMM
    #undef LIF_STEP
}

extern "C" void kernel_launch(void* const* d_in, const int* in_sizes, int n_in,
                              void* d_out, int out_size) {
    const float* x  = (const float*)d_in[0];
    const float* W1 = (const float*)d_in[1];
    const float* b1 = (const float*)d_in[2];
    const float* W2 = (const float*)d_in[3];
    const float* b2 = (const float*)d_in[4];
    const float* W3 = (const float*)d_in[5];
    const float* b3 = (const float*)d_in[6];
    snn_all<<<BATCH / 8, 256>>>(x, W1, b1, W2, b2, W3, b3, (float*)d_out);
}